// round 14
// baseline (speedup 1.0000x reference)
#include <cuda_runtime.h>
#include <cuda_bf16.h>

#define NTHR 256
#define ST_SIZE 4096

// XOR-swizzled state: addr = (i<<9)|(j<<6)|((k&6)<<3) | (c0(i)^c1(j)^c2(k)^c3(l))
__device__ __forceinline__ int hi_c(int m, int x) {
    return m==0 ? (x<<9) : m==1 ? (x<<6) : m==2 ? ((x&6)<<3) : 0;
}
__device__ __forceinline__ int c16_c(int m, int x) {
    return m==0 ? x
         : m==1 ? 9*(x&1)
         : m==2 ? (((x&1)<<3) ^ (x&4) ^ (x&2))
         : (x ^ ((x&4)<<1));
}
__device__ __forceinline__ int addr4i(int i,int j,int k,int l){
    return (i<<9)|(j<<6)|((k&6)<<3)
         | ((c16_c(0,i) ^ c16_c(1,j) ^ c16_c(2,k) ^ c16_c(3,l)) & 15);
}

__device__ __align__(16) float2 g_bs[48][376];
__device__ __align__(16) float2 g_sq[16][64];
__device__ __align__(16) float2 g_dp[16][64];

__constant__ int OFFP[16] = {0,2,6,18,34,64,100,156,220,276,312,342,358,370,374,376};
__constant__ int c_PI[6] = {0,0,0,1,1,2};
__constant__ int c_PJ[6] = {1,2,3,2,3,3};

__device__ __forceinline__ float2 cmul(float2 a, float2 b) {
    return make_float2(fmaf(a.x, b.x, -a.y * b.y), fmaf(a.x, b.y, a.y * b.x));
}
__device__ __forceinline__ void cmac(float2& acc, float ur, float ui, const float2 s) {
    acc.x = fmaf(ur, s.x, acc.x); acc.x = fmaf(-ui, s.y, acc.x);
    acc.y = fmaf(ur, s.y, acc.y); acc.y = fmaf(ui, s.x, acc.y);
}

// ===========================================================================
// Precompute (identical to the passing R11/R12 kernel).
// ===========================================================================
__global__ __launch_bounds__(NTHR) void precompute_kernel(
    const float* __restrict__ th1, const float* __restrict__ ph1,
    const float* __restrict__ th2, const float* __restrict__ ph2,
    const float* __restrict__ dr,  const float* __restrict__ dphi,
    const float* __restrict__ sr,  const float* __restrict__ sphi,
    const float* __restrict__ kerr)
{
    __shared__ float2 T[4096 + 128];
    int bid = blockIdx.x, t = threadIdx.x;

    if (bid < 48) {
        int l = bid / 12, rem = bid % 12, intf = rem / 6, p = rem % 6;
        int i = c_PI[p], j = c_PJ[p];
        const float* th = intf ? th2 : th1;
        const float* PH = (intf ? ph2 : ph1) + l * 16;
        float theta = th[l*16 + i*4 + j];
        float phiv  = PH[i*4 + j];
        float cp, sp; sincosf(phiv, &sp, &cp);
        const float scale = 1.0f / 256.0f;

        for (int e = t; e < 4096; e += NTHR) {
            int r = e >> 6, c = e & 63;
            T[e] = make_float2((r == c) ? 1.f : 0.f, 0.f);
        }
        __syncthreads();

        for (int k = 10; k >= 1; k--) {
            float invk = 1.0f / (float)k;
            float2 Cn[16];
            #pragma unroll
            for (int q = 0; q < 16; q++) {
                int e = t * 16 + q;
                int r = e >> 6, c = e & 63;
                int a = r >> 3, b = r & 7;
                float2 acc = make_float2(0.f, 0.f);
                if (a < 7 && b > 0) {
                    float coef = theta * sqrtf((float)((a + 1) * b)) * scale;
                    float2 co = make_float2(coef * cp, coef * sp);
                    float2 pr = cmul(co, T[((a + 1) * 8 + (b - 1)) * 64 + c]);
                    acc.x += pr.x; acc.y += pr.y;
                }
                if (a > 0 && b < 7) {
                    float coef = theta * sqrtf((float)(a * (b + 1))) * scale;
                    float2 co = make_float2(-coef * cp, coef * sp);
                    float2 pr = cmul(co, T[((a - 1) * 8 + (b + 1)) * 64 + c]);
                    acc.x += pr.x; acc.y += pr.y;
                }
                acc.x *= invk; acc.y *= invk;
                if (r == c) acc.x += 1.0f;
                Cn[q] = acc;
            }
            __syncthreads();
            #pragma unroll
            for (int q = 0; q < 16; q++) T[t * 16 + q] = Cn[q];
            __syncthreads();
        }
        for (int sq = 0; sq < 8; sq++) {
            float2 Cn[16];
            #pragma unroll
            for (int q = 0; q < 16; q++) {
                int e = t * 16 + q;
                int r = e >> 6, c = e & 63;
                float2 acc = make_float2(0.f, 0.f);
                for (int m = 0; m < 64; m++) {
                    float2 av = T[r * 64 + m];
                    float2 bv = T[m * 64 + c];
                    acc.x = fmaf(av.x, bv.x, acc.x); acc.x = fmaf(-av.y, bv.y, acc.x);
                    acc.y = fmaf(av.x, bv.y, acc.y); acc.y = fmaf(av.y, bv.x, acc.y);
                }
                Cn[q] = acc;
            }
            __syncthreads();
            #pragma unroll
            for (int q = 0; q < 16; q++) T[t * 16 + q] = Cn[q];
            __syncthreads();
        }

        float a4[4] = {PH[0], PH[5], PH[10], PH[15]};
        float b4[4] = {0.f, 0.f, 0.f, 0.f};
        if (intf == 0 && l > 0) {
            b4[0] = kerr[(l-1)*4+0]; b4[1] = kerr[(l-1)*4+1];
            b4[2] = kerr[(l-1)*4+2]; b4[3] = kerr[(l-1)*4+3];
        }
        for (int pp = 0; pp < p; pp++) {
            int ii = c_PI[pp], jj = c_PJ[pp];
            a4[ii] = 0.f; b4[ii] = 0.f;
            a4[jj] = PH[jj*4 + ii]; b4[jj] = 0.f;
        }
        float Ai = a4[i], Bi = b4[i], Aj = a4[j], Bj = b4[j];

        for (int e2 = t; e2 < 376; e2 += NTHR) {
            int n = 0;
            #pragma unroll
            for (int m = 1; m < 15; m++) if (e2 >= OFFP[m]) n = m;
            int K = 8 - ((n < 7) ? (7 - n) : (n - 7));
            int RK = K + (K & 1);
            int lo = (n > 7) ? (n - 7) : 0;
            int loc = e2 - OFFP[n];
            int aidx = loc / RK, cidx = loc % RK;
            float2 v = make_float2(0.f, 0.f);
            if (cidx < K) {
                int a = lo + aidx, b = n - a, c = lo + cidx, d = n - c;
                v = T[(a * 8 + b) * 64 + (c * 8 + d)];
                float P = Ai * (float)c + Bi * (float)(c * c)
                        + Aj * (float)d + Bj * (float)(d * d);
                float sn, cn; sincosf(P, &sn, &cn);
                v = cmul(v, make_float2(cn, sn));
            }
            g_bs[bid][e2] = v;
        }
    } else {
        int idx = bid - 48;
        bool is_sq = (idx < 16);
        int li = is_sq ? idx : (idx - 16);
        int l2 = li >> 2, w = li & 3;
        float2* Tsm = T;
        float2* Hsm = T + 64;
        int r = t >> 3, c = t & 7;

        if (t < 64) {
            float2 h = make_float2(0.f, 0.f);
            if (is_sq) {
                float rv = sr[li], pv = sphi[li];
                float cps, sps; sincosf(pv, &sps, &cps);
                float zr = rv * cps, zi = rv * sps;
                if (c == r + 2) {
                    float f = sqrtf((float)((r + 1) * (r + 2)));
                    h.x += 0.5f * zr * f;  h.y += -0.5f * zi * f;
                }
                if (c + 2 == r) {
                    float f = sqrtf((float)((c + 1) * (c + 2)));
                    h.x += -0.5f * zr * f; h.y += -0.5f * zi * f;
                }
            } else {
                float rv = dr[li], pv = dphi[li];
                float mm = rv * cosf(pv);
                float thp = rv * sinf(pv);
                float cth, sth; sincosf(thp, &sth, &cth);
                float ax = mm * cth, ay = mm * sth;
                if (c + 1 == r) { float f = sqrtf((float)r); h.x += ax * f; h.y += ay * f; }
                if (c == r + 1) { float f = sqrtf((float)(r + 1)); h.x += -ax * f; h.y += ay * f; }
            }
            const float sc16 = 1.0f / 16.0f;
            h.x *= sc16; h.y *= sc16;
            Hsm[t] = h;
            Tsm[t] = make_float2((r == c) ? 1.f : 0.f, 0.f);
        }
        __syncthreads();

        for (int k = 10; k >= 1; k--) {
            float2 v = make_float2(0.f, 0.f);
            if (t < 64) {
                #pragma unroll
                for (int m = 0; m < 8; m++) {
                    float2 hm = Hsm[r * 8 + m];
                    float2 tm = Tsm[m * 8 + c];
                    v.x = fmaf(hm.x, tm.x, v.x); v.x = fmaf(-hm.y, tm.y, v.x);
                    v.y = fmaf(hm.x, tm.y, v.y); v.y = fmaf(hm.y, tm.x, v.y);
                }
                float ik = 1.0f / (float)k;
                v.x *= ik; v.y *= ik;
                if (r == c) v.x += 1.0f;
            }
            __syncthreads();
            if (t < 64) Tsm[t] = v;
            __syncthreads();
        }
        for (int sq = 0; sq < 4; sq++) {
            float2 v = make_float2(0.f, 0.f);
            if (t < 64) {
                #pragma unroll
                for (int m = 0; m < 8; m++) {
                    float2 av = Tsm[r * 8 + m];
                    float2 bv = Tsm[m * 8 + c];
                    v.x = fmaf(av.x, bv.x, v.x); v.x = fmaf(-av.y, bv.y, v.x);
                    v.y = fmaf(av.x, bv.y, v.y); v.y = fmaf(av.y, bv.x, v.y);
                }
            }
            __syncthreads();
            if (t < 64) Tsm[t] = v;
            __syncthreads();
        }
        if (t < 64) {
            const float* PH = (is_sq ? ph1 : ph2) + l2 * 16;
            float a4[4] = {PH[0], PH[5], PH[10], PH[15]};
            float b4[4] = {0.f, 0.f, 0.f, 0.f};
            if (is_sq && l2 > 0) {
                b4[0] = kerr[(l2-1)*4+0]; b4[1] = kerr[(l2-1)*4+1];
                b4[2] = kerr[(l2-1)*4+2]; b4[3] = kerr[(l2-1)*4+3];
            }
            for (int pp = 0; pp < 6; pp++) {
                int ii = c_PI[pp], jj = c_PJ[pp];
                a4[ii] = 0.f; b4[ii] = 0.f;
                a4[jj] = PH[jj*4 + ii]; b4[jj] = 0.f;
            }
            float P = a4[w] * (float)c + b4[w] * (float)(c * c);
            float sn, cn; sincosf(P, &sn, &cn);
            float2 v = cmul(Tsm[t], make_float2(cn, sn));
            if (is_sq) g_sq[li][t] = v;
            else       g_dp[li][t] = v;
        }
    }
}

// ===========================================================================
// BS row-slice: rows [R0,R0+NR) of block N for this lane's 2 fibers.
// Double-buffered: reads src, writes dst. F4B = block base in float4 units.
// ===========================================================================
template<int K,int N,int M1,int M2,int R0,int NR,int F4B>
__device__ __forceinline__ void bs_slice(const float4* __restrict__ U4,
    int SH1,int SL1,int SH2,int SL2,
    const float2* __restrict__ src, float2* __restrict__ dst)
{
    constexpr int LO = (N > 7) ? (N - 7) : 0;
    constexpr int R4 = (K + 1) / 2;
    float2 in1[K], in2[K];
    #pragma unroll
    for (int c = 0; c < K; c++) {
        int AH = hi_c(M1, LO + c) + hi_c(M2, N - LO - c);
        int AL = c16_c(M1, LO + c) ^ c16_c(M2, N - LO - c);
        in1[c] = src[SH1 + AH + (SL1 ^ AL)];
        in2[c] = src[SH2 + AH + (SL2 ^ AL)];
    }
    #pragma unroll
    for (int r = R0; r < R0 + NR; r++) {
        float2 a1 = make_float2(0.f, 0.f), a2 = make_float2(0.f, 0.f);
        #pragma unroll
        for (int q = 0; q < R4; q++) {
            float4 u = __ldg(U4 + F4B + r * R4 + q);
            cmac(a1, u.x, u.y, in1[2 * q]);
            cmac(a2, u.x, u.y, in2[2 * q]);
            if (2 * q + 1 < K) {
                cmac(a1, u.z, u.w, in1[2 * q + 1]);
                cmac(a2, u.z, u.w, in2[2 * q + 1]);
            }
        }
        int AH = hi_c(M1, LO + r) + hi_c(M2, N - LO - r);
        int AL = c16_c(M1, LO + r) ^ c16_c(M2, N - LO - r);
        dst[SH1 + AH + (SL1 ^ AL)] = a1;
        dst[SH2 + AH + (SL2 ^ AL)] = a2;
    }
}

// Full BS gate for pair P: 8 warps, balanced row bins (43+-1 cmacs/fiber).
template<int P>
__device__ __noinline__ void bs_gate(const float4* __restrict__ U4, int wid, int lane,
                                     const float2* __restrict__ src,
                                     float2* __restrict__ dst)
{
    constexpr int M1 = (P < 3) ? 0 : (P < 5) ? 1 : 2;
    constexpr int M2 = (P == 0) ? 1 : (P == 1 || P == 3) ? 2 : 3;
    constexpr int MA = (P == 0) ? 2 : (P == 1 || P == 2 || P == 5) ? 1 : 0;
    constexpr int MB = (P == 2 || P == 4) ? 2 : (P == 5) ? 0 : 3;
    int q0 = lane >> 3, q1 = lane & 7;
    int q0b = q0 + 4;
    int xa = q0, xb = q0b;
    if (P == 3) {
        xa = ((q0  & 6) >> 1) | ((q0  & 1) << 2);
        xb = ((q0b & 6) >> 1) | ((q0b & 1) << 2);
    }
    int SH1 = hi_c(MA, xa) + hi_c(MB, q1), SL1 = c16_c(MA, xa) ^ c16_c(MB, q1);
    int SH2 = hi_c(MA, xb) + hi_c(MB, q1), SL2 = c16_c(MA, xb) ^ c16_c(MB, q1);

    switch (wid) {
    case 0:
        bs_slice<7, 6,M1,M2,0,6, 50>(U4,SH1,SL1,SH2,SL2,src,dst);
        bs_slice<1, 0,M1,M2,0,1,  0>(U4,SH1,SL1,SH2,SL2,src,dst);
        break;
    case 1:
        bs_slice<7, 6,M1,M2,6,1, 50>(U4,SH1,SL1,SH2,SL2,src,dst);
        bs_slice<6, 5,M1,M2,0,6, 32>(U4,SH1,SL1,SH2,SL2,src,dst);
        break;
    case 2:
        bs_slice<7, 8,M1,M2,0,6,110>(U4,SH1,SL1,SH2,SL2,src,dst);
        bs_slice<1,14,M1,M2,0,1,187>(U4,SH1,SL1,SH2,SL2,src,dst);
        break;
    case 3:
        bs_slice<7, 8,M1,M2,6,1,110>(U4,SH1,SL1,SH2,SL2,src,dst);
        bs_slice<6, 9,M1,M2,0,6,138>(U4,SH1,SL1,SH2,SL2,src,dst);
        break;
    case 4:
        bs_slice<8, 7,M1,M2,0,5, 78>(U4,SH1,SL1,SH2,SL2,src,dst);
        bs_slice<3, 2,M1,M2,0,1,  3>(U4,SH1,SL1,SH2,SL2,src,dst);
        break;
    case 5:
        bs_slice<8, 7,M1,M2,5,3, 78>(U4,SH1,SL1,SH2,SL2,src,dst);
        bs_slice<5, 4,M1,M2,0,4, 17>(U4,SH1,SL1,SH2,SL2,src,dst);
        break;
    case 6:
        bs_slice<5, 4,M1,M2,4,1, 17>(U4,SH1,SL1,SH2,SL2,src,dst);
        bs_slice<5,10,M1,M2,0,5,156>(U4,SH1,SL1,SH2,SL2,src,dst);
        bs_slice<4, 3,M1,M2,0,3,  9>(U4,SH1,SL1,SH2,SL2,src,dst);
        break;
    default:
        bs_slice<4, 3,M1,M2,3,1,  9>(U4,SH1,SL1,SH2,SL2,src,dst);
        bs_slice<4,11,M1,M2,0,4,171>(U4,SH1,SL1,SH2,SL2,src,dst);
        bs_slice<3, 2,M1,M2,1,2,  3>(U4,SH1,SL1,SH2,SL2,src,dst);
        bs_slice<3,12,M1,M2,0,3,179>(U4,SH1,SL1,SH2,SL2,src,dst);
        bs_slice<2, 1,M1,M2,0,2,  1>(U4,SH1,SL1,SH2,SL2,src,dst);
        bs_slice<2,13,M1,M2,0,2,185>(U4,SH1,SL1,SH2,SL2,src,dst);
        break;
    }
}

// Single-mode 8x8 gate, in place on buffer; 2 fibers/thread (as R12).
template<int MODE>
__device__ __noinline__ void apply1g_t(float2* __restrict__ st,
                                       const float4* __restrict__ U4, int t)
{
    int SH1, SL1, SH2, SL2;
    if (MODE == 0) {
        int l_ = t & 7, k_ = (t >> 3) & 7, j_ = (t >> 6) & 3;
        SH1 = hi_c(1,j_)   + hi_c(2,k_) + hi_c(3,l_);
        SL1 = c16_c(1,j_)   ^ c16_c(2,k_) ^ c16_c(3,l_);
        SH2 = hi_c(1,j_+4) + hi_c(2,k_) + hi_c(3,l_);
        SL2 = c16_c(1,j_+4) ^ c16_c(2,k_) ^ c16_c(3,l_);
    } else if (MODE == 1) {
        int l_ = t & 7, i_ = (((t >> 3) & 1) << 2) | ((t >> 4) & 3), k_ = (t >> 6) & 3;
        SH1 = hi_c(0,i_) + hi_c(2,k_)   + hi_c(3,l_);
        SL1 = c16_c(0,i_) ^ c16_c(2,k_)   ^ c16_c(3,l_);
        SH2 = hi_c(0,i_) + hi_c(2,k_+4) + hi_c(3,l_);
        SL2 = c16_c(0,i_) ^ c16_c(2,k_+4) ^ c16_c(3,l_);
    } else if (MODE == 2) {
        int l_ = t & 7, j_ = ((t >> 3) & 1) | (((t >> 4) & 3) << 1), i_ = (t >> 6) & 3;
        SH1 = hi_c(0,i_)   + hi_c(1,j_) + hi_c(3,l_);
        SL1 = c16_c(0,i_)   ^ c16_c(1,j_) ^ c16_c(3,l_);
        SH2 = hi_c(0,i_+4) + hi_c(1,j_) + hi_c(3,l_);
        SL2 = c16_c(0,i_+4) ^ c16_c(1,j_) ^ c16_c(3,l_);
    } else {
        int i_ = t & 7, j_ = ((t >> 3) & 1) | (((t >> 4) & 3) << 1), k_ = (t >> 6) & 3;
        SH1 = hi_c(0,i_) + hi_c(1,j_) + hi_c(2,k_);
        SL1 = c16_c(0,i_) ^ c16_c(1,j_) ^ c16_c(2,k_);
        SH2 = hi_c(0,i_) + hi_c(1,j_) + hi_c(2,k_+4);
        SL2 = c16_c(0,i_) ^ c16_c(1,j_) ^ c16_c(2,k_+4);
    }

    float2 sva[8], svb[8];
    #pragma unroll
    for (int c = 0; c < 8; c++) {
        int AH = hi_c(MODE, c), AL = c16_c(MODE, c);
        sva[c] = st[SH1 + AH + (SL1 ^ AL)];
        svb[c] = st[SH2 + AH + (SL2 ^ AL)];
    }
    #pragma unroll
    for (int o = 0; o < 8; o++) {
        float2 aa = make_float2(0.f, 0.f), ab = make_float2(0.f, 0.f);
        #pragma unroll
        for (int q = 0; q < 4; q++) {
            float4 u = __ldg(U4 + o * 4 + q);
            cmac(aa, u.x, u.y, sva[2 * q]); cmac(aa, u.z, u.w, sva[2 * q + 1]);
            cmac(ab, u.x, u.y, svb[2 * q]); cmac(ab, u.z, u.w, svb[2 * q + 1]);
        }
        int AH = hi_c(MODE, o), AL = c16_c(MODE, o);
        st[SH1 + AH + (SL1 ^ AL)] = aa;
        st[SH2 + AH + (SL2 ^ AL)] = ab;
    }
}

// ===========================================================================
// Main kernel: one CTA per batch element, double-buffered BS, in-place 1g.
// ===========================================================================
__global__ __launch_bounds__(NTHR, 3) void qnn_main(
    const float* __restrict__ x, float* __restrict__ out)
{
    extern __shared__ float2 sm[];
    float2* bufA = sm;
    float2* bufB = sm + ST_SIZE;
    float* enc = (float*)(sm + 2 * ST_SIZE);   // encH[256] encA[256] encB[256] red[32]
    float* encH = enc, *encA = enc + 256, *encB = enc + 512;
    float* red = enc + 768;

    int b = blockIdx.x, t = threadIdx.x;
    int wid = t >> 5, lane = t & 31;

    // ---- per-sample encoding expm: E_g = expm(x_g (AD - A)), real 8x8 ----
    {
        int g = t >> 6, e = t & 63, r = e >> 3, c = e & 7;
        float xv = __ldg(&x[b * 4 + g]);
        float sc = xv * (1.0f / 64.0f);   // 6 squarings
        float h = 0.f;
        if (c == r - 1) h = sc * sqrtf((float)r);
        else if (c == r + 1) h = -sc * sqrtf((float)(r + 1));
        encH[g * 64 + e] = h;
        encA[g * 64 + e] = (r == c) ? 1.f : 0.f;
        __syncthreads();

        float* Ta = encA + g * 64;
        float* Tb = encB + g * 64;
        for (int k = 9; k >= 1; k--) {
            float acc = 0.f;
            #pragma unroll
            for (int m = 0; m < 8; m++)
                acc = fmaf(encH[g * 64 + r * 8 + m], Ta[m * 8 + c], acc);
            float v = acc / (float)k + ((r == c) ? 1.f : 0.f);
            Tb[e] = v;
            __syncthreads();
            float* tmp = Ta; Ta = Tb; Tb = tmp;
        }
        for (int sq = 0; sq < 6; sq++) {
            float acc = 0.f;
            #pragma unroll
            for (int m = 0; m < 8; m++) acc = fmaf(Ta[r * 8 + m], Ta[m * 8 + c], acc);
            Tb[e] = acc;
            __syncthreads();
            float* tmp = Ta; Ta = Tb; Tb = tmp;
        }
        // final matrix lives in encB region (15 swaps)
    }

    // ---- init state into bufA: outer product of E_g column 0 ----
    {
        int i_ = t & 7, j_ = ((t >> 3) & 1) | (((t >> 4) & 3) << 1), k_ = (t >> 6) & 3;
        float e0 = encB[0 * 64 + i_ * 8];
        float e1 = encB[1 * 64 + j_ * 8];
        #pragma unroll
        for (int kk = 0; kk < 2; kk++) {
            int k2 = k_ + 4 * kk;
            float e01 = e0 * e1 * encB[2 * 64 + k2 * 8];
            #pragma unroll
            for (int l2 = 0; l2 < 8; l2++)
                bufA[addr4i(i_, j_, k2, l2)] =
                    make_float2(e01 * encB[3 * 64 + l2 * 8], 0.f);
        }
    }
    __syncthreads();

    // ---- circuit: BS gates ping-pong A->B->A...; 1g in place on A ----
    #pragma unroll 1
    for (int l = 0; l < 4; l++) {
        #pragma unroll 1
        for (int hh = 0; hh < 2; hh++) {
            const float4* G0 = (const float4*)g_bs[l * 12 + hh * 6];
            bs_gate<0>(G0 + 0 * 188, wid, lane, bufA, bufB); __syncthreads();
            bs_gate<1>(G0 + 1 * 188, wid, lane, bufB, bufA); __syncthreads();
            bs_gate<2>(G0 + 2 * 188, wid, lane, bufA, bufB); __syncthreads();
            bs_gate<3>(G0 + 3 * 188, wid, lane, bufB, bufA); __syncthreads();
            bs_gate<4>(G0 + 4 * 188, wid, lane, bufA, bufB); __syncthreads();
            bs_gate<5>(G0 + 5 * 188, wid, lane, bufB, bufA); __syncthreads();
            const float2* GB = hh ? g_dp[l * 4] : g_sq[l * 4];
            apply1g_t<0>(bufA, (const float4*)(GB + 0 * 64), t); __syncthreads();
            apply1g_t<1>(bufA, (const float4*)(GB + 1 * 64), t); __syncthreads();
            apply1g_t<2>(bufA, (const float4*)(GB + 2 * 64), t); __syncthreads();
            apply1g_t<3>(bufA, (const float4*)(GB + 3 * 64), t); __syncthreads();
        }
    }

    // ---- expectations <n_w> from bufA ----
    float ev0 = 0.f, ev1 = 0.f, ev2 = 0.f, ev3 = 0.f;
    {
        int i_ = t & 7, j_ = ((t >> 3) & 1) | (((t >> 4) & 3) << 1), k_ = (t >> 6) & 3;
        #pragma unroll
        for (int kk = 0; kk < 2; kk++) {
            int k2 = k_ + 4 * kk;
            #pragma unroll
            for (int l2 = 0; l2 < 8; l2++) {
                float2 a = bufA[addr4i(i_, j_, k2, l2)];
                float p = a.x * a.x + a.y * a.y;
                ev0 = fmaf(p, (float)i_, ev0);
                ev1 = fmaf(p, (float)j_, ev1);
                ev2 = fmaf(p, (float)k2, ev2);
                ev3 = fmaf(p, (float)l2, ev3);
            }
        }
    }
    #pragma unroll
    for (int off2 = 16; off2; off2 >>= 1) {
        ev0 += __shfl_down_sync(0xFFFFFFFFu, ev0, off2);
        ev1 += __shfl_down_sync(0xFFFFFFFFu, ev1, off2);
        ev2 += __shfl_down_sync(0xFFFFFFFFu, ev2, off2);
        ev3 += __shfl_down_sync(0xFFFFFFFFu, ev3, off2);
    }
    if (lane == 0) {
        red[0 * 8 + wid] = ev0; red[1 * 8 + wid] = ev1;
        red[2 * 8 + wid] = ev2; red[3 * 8 + wid] = ev3;
    }
    __syncthreads();
    if (t < 4) {
        float s = 0.f;
        #pragma unroll
        for (int wv = 0; wv < 8; wv++) s += red[t * 8 + wv];
        out[b * 4 + t] = s;
    }
}

extern "C" void kernel_launch(void* const* d_in, const int* in_sizes, int n_in,
                              void* d_out, int out_size) {
    const float* x    = (const float*)d_in[0];
    const float* th1  = (const float*)d_in[1];
    const float* ph1  = (const float*)d_in[2];
    const float* th2  = (const float*)d_in[3];
    const float* ph2  = (const float*)d_in[4];
    const float* dr   = (const float*)d_in[5];
    const float* dphi = (const float*)d_in[6];
    const float* sr   = (const float*)d_in[7];
    const float* sphi = (const float*)d_in[8];
    const float* kerr = (const float*)d_in[9];
    float* out = (float*)d_out;
    int Bn = in_sizes[0] / 4;

    int smem_bytes = 2 * ST_SIZE * (int)sizeof(float2) + (768 + 32) * (int)sizeof(float);
    cudaFuncSetAttribute(qnn_main, cudaFuncAttributeMaxDynamicSharedMemorySize, smem_bytes);

    precompute_kernel<<<80, NTHR>>>(th1, ph1, th2, ph2, dr, dphi, sr, sphi, kerr);
    qnn_main<<<Bn, NTHR, smem_bytes>>>(x, out);
}

// round 15
// speedup vs baseline: 1.5086x; 1.5086x over previous
#include <cuda_runtime.h>
#include <cuda_bf16.h>

#define NTHR 256
// affine smem strides (float2 units), residues mod 16 = (8,5,11,1)  [R8 layout]
#define S0 680
#define S1 85
#define S2 11
#define ST_SIZE 5440

// Real-matrix gate storage.
// BS: block-diagonal real, block n: K=8-|n-7| rows, row padded to RK4=(K<=4?4:8) floats.
__device__ __align__(16) float  g_bsr[48][432];
__device__ __align__(16) float  g_1gr[32][64];    // 8x8 real, [out*8+in]; 0..15 squeeze, 16..31 disp
__device__ __align__(16) float2 g_wbs[48][64];    // BS input phase table w[c*8+d]
__device__ __align__(16) float2 g_w1[32][8];      // 1g input phase table

__constant__ int OFFRc[16] = {0,4,12,24,40,80,128,184,248,304,352,392,408,420,428,432};
__constant__ int c_PI[6] = {0,0,0,1,1,2};
__constant__ int c_PJ[6] = {1,2,3,2,3,3};
__constant__ int c_SA[6] = {680,680,680,85,85,11};
__constant__ int c_SB[6] = {85,11,1,11,1,1};
__constant__ int c_Q0[6] = {11,85,85,680,680,680};
__constant__ int c_Q1[6] = {1,1,11,1,9,85};   // NOTE: fixed below (see c_Q1v)
__constant__ int c_Q1v[6] = {1,1,11,1,11,85};
__constant__ int c1g_SM[4] = {680,85,11,1};
__constant__ int c1g_B0[4] = {1,11,85,11};
__constant__ int c1g_B1[4] = {85,680,680,680};
__constant__ int c1g_B2[4] = {11,1,1,85};
__constant__ int c1g_P[4]  = {44,4,4,340};

__device__ __forceinline__ float2 cmul(float2 a, float2 b) {
    return make_float2(fmaf(a.x, b.x, -a.y * b.y), fmaf(a.x, b.y, a.y * b.x));
}
__device__ __forceinline__ void rmac(float2& a, float c, const float2 s) {
    a.x = fmaf(c, s.x, a.x); a.y = fmaf(c, s.y, a.y);
}

// ---------------------------------------------------------------------------
// Scalar phase simulator: pending diagonal phases per mode, angle tables.
// Gate ids per layer l: BS1 l*20+0..5, squeeze +6..9, BS2 +10..15, disp +16..19.
// ---------------------------------------------------------------------------
__device__ void sim_phases(const float* ph1, const float* ph2, const float* sphi,
                           const float* dr, const float* dphi, const float* kerr,
                           int target, float* ioA, float* ioB)
{
    float pend[4][8];
    for (int m = 0; m < 4; m++) for (int n = 0; n < 8; n++) pend[m][n] = 0.f;
    int id = 0;
    for (int l = 0; l < 4; l++) {
        for (int h = 0; h < 2; h++) {
            const float* P = (h ? ph2 : ph1) + l * 16;
            for (int m = 0; m < 4; m++)
                for (int n = 0; n < 8; n++) pend[m][n] += P[m*4+m] * (float)n;
            for (int p = 0; p < 6; p++) {
                int i = c_PI[p], j = c_PJ[p];
                float ph = P[i*4+j];
                if (id == target) {
                    for (int n = 0; n < 8; n++) {
                        ioA[n] = pend[i][n] + ph * (float)n;  // input D_phi on mode i
                        ioB[n] = pend[j][n];
                    }
                    return;
                }
                for (int n = 0; n < 8; n++) pend[i][n] = -ph * (float)n;   // output D_-phi
                for (int n = 0; n < 8; n++) pend[j][n] = P[j*4+i] * (float)n; // post-rotation
                id++;
            }
            if (h == 0) {
                for (int w = 0; w < 4; w++) {
                    float ps = sphi[l*4+w];
                    if (id == target) {
                        for (int n = 0; n < 8; n++) ioA[n] = pend[w][n] - 0.5f*ps*(float)n;
                        return;
                    }
                    for (int n = 0; n < 8; n++) pend[w][n] = 0.5f*ps*(float)n;
                    id++;
                }
            } else {
                for (int w = 0; w < 4; w++) {
                    float th = dr[l*4+w] * sinf(dphi[l*4+w]);
                    if (id == target) {
                        for (int n = 0; n < 8; n++) ioA[n] = pend[w][n] - th*(float)n;
                        return;
                    }
                    for (int n = 0; n < 8; n++) pend[w][n] = th*(float)n;
                    id++;
                }
                for (int w = 0; w < 4; w++)
                    for (int n = 0; n < 8; n++) pend[w][n] += kerr[l*4+w]*(float)(n*n);
            }
        }
    }
}

// ===========================================================================
// Precompute: 80 blocks; real expm matrices + input-phase tables.
// ===========================================================================
__global__ __launch_bounds__(NTHR) void precompute_kernel(
    const float* __restrict__ th1, const float* __restrict__ ph1,
    const float* __restrict__ th2, const float* __restrict__ ph2,
    const float* __restrict__ dr,  const float* __restrict__ dphi,
    const float* __restrict__ sr,  const float* __restrict__ sphi,
    const float* __restrict__ kerr)
{
    __shared__ float2 T[4096 + 128];
    __shared__ float sio[2][8];
    int bid = blockIdx.x, t = threadIdx.x;

    // target gate id for the phase simulator
    int target;
    if (bid < 48) {
        int l = bid / 12, rem = bid % 12;
        target = l * 20 + (rem / 6) * 10 + (rem % 6);
    } else if (bid < 64) {
        int li = bid - 48; target = (li >> 2) * 20 + 6 + (li & 3);
    } else {
        int li = bid - 64; target = (li >> 2) * 20 + 16 + (li & 3);
    }
    if (t == 0) sim_phases(ph1, ph2, sphi, dr, dphi, kerr, target, sio[0], sio[1]);
    __syncthreads();

    if (bid < 48) {
        int l = bid / 12, rem = bid % 12, intf = rem / 6, p = rem % 6;
        int i = c_PI[p], j = c_PJ[p];
        const float* th = intf ? th2 : th1;
        float theta = th[l*16 + i*4 + j];
        const float scale = 1.0f / 256.0f;   // 8 squarings

        for (int e = t; e < 4096; e += NTHR) {
            int r = e >> 6, c = e & 63;
            T[e] = make_float2((r == c) ? 1.f : 0.f, 0.f);
        }
        __syncthreads();

        // Taylor Horner with REAL sparse H0 (phi removed), K=10
        for (int k = 10; k >= 1; k--) {
            float invk = 1.0f / (float)k;
            float2 Cn[16];
            #pragma unroll
            for (int q = 0; q < 16; q++) {
                int e = t * 16 + q;
                int r = e >> 6, c = e & 63;
                int a = r >> 3, b = r & 7;
                float2 acc = make_float2(0.f, 0.f);
                if (a < 7 && b > 0) {
                    float coef = theta * sqrtf((float)((a + 1) * b)) * scale;
                    float2 s = T[((a + 1) * 8 + (b - 1)) * 64 + c];
                    acc.x += coef * s.x; acc.y += coef * s.y;
                }
                if (a > 0 && b < 7) {
                    float coef = -theta * sqrtf((float)(a * (b + 1))) * scale;
                    float2 s = T[((a - 1) * 8 + (b + 1)) * 64 + c];
                    acc.x += coef * s.x; acc.y += coef * s.y;
                }
                acc.x *= invk; acc.y *= invk;
                if (r == c) acc.x += 1.0f;
                Cn[q] = acc;
            }
            __syncthreads();
            #pragma unroll
            for (int q = 0; q < 16; q++) T[t * 16 + q] = Cn[q];
            __syncthreads();
        }
        for (int sq = 0; sq < 8; sq++) {
            float2 Cn[16];
            #pragma unroll
            for (int q = 0; q < 16; q++) {
                int e = t * 16 + q;
                int r = e >> 6, c = e & 63;
                float2 acc = make_float2(0.f, 0.f);
                for (int m = 0; m < 64; m++) {
                    float2 av = T[r * 64 + m];
                    float2 bv = T[m * 64 + c];
                    acc.x = fmaf(av.x, bv.x, acc.x); acc.x = fmaf(-av.y, bv.y, acc.x);
                    acc.y = fmaf(av.x, bv.y, acc.y); acc.y = fmaf(av.y, bv.x, acc.y);
                }
                Cn[q] = acc;
            }
            __syncthreads();
            #pragma unroll
            for (int q = 0; q < 16; q++) T[t * 16 + q] = Cn[q];
            __syncthreads();
        }

        // pack REAL matrix (row padded to RK4 floats)
        for (int e2 = t; e2 < 432; e2 += NTHR) {
            int n = 0;
            #pragma unroll
            for (int m = 1; m < 15; m++) if (e2 >= OFFRc[m]) n = m;
            int K = 8 - ((n < 7) ? (7 - n) : (n - 7));
            int RK4 = (K <= 4) ? 4 : 8;
            int LO = (n > 7) ? (n - 7) : 0;
            int loc = e2 - OFFRc[n];
            int a = loc / RK4, col = loc % RK4;
            float v = 0.f;
            if (col < K) {
                int A = LO + a, Bq = n - A, C = LO + col, Dq = n - C;
                v = T[(A * 8 + Bq) * 64 + (C * 8 + Dq)].x;
            }
            g_bsr[bid][e2] = v;
        }
        // input phase table w[c*8+d]
        if (t < 64) {
            float ang = sio[0][t >> 3] + sio[1][t & 7];
            float sn, cn; sincosf(ang, &sn, &cn);
            g_wbs[bid][t] = make_float2(cn, sn);
        }
    } else {
        int idx = bid - 48;
        bool is_sq = (idx < 16);
        int li = is_sq ? idx : (idx - 16);
        float2* Tsm = T;
        float2* Hsm = T + 64;
        int r = t >> 3, c = t & 7;

        if (t < 64) {
            float h = 0.f;
            if (is_sq) {
                float rv = sr[li];                       // real squeeze S(r)
                if (c == r + 2) h += 0.5f * rv * sqrtf((float)((r + 1) * (r + 2)));
                if (c + 2 == r) h += -0.5f * rv * sqrtf((float)((c + 1) * (c + 2)));
            } else {
                float mm = dr[li] * cosf(dphi[li]);      // real displacement D(m)
                if (c + 1 == r) h += mm * sqrtf((float)r);
                if (c == r + 1) h += -mm * sqrtf((float)(r + 1));
            }
            h *= (1.0f / 16.0f);   // 4 squarings
            Hsm[t] = make_float2(h, 0.f);
            Tsm[t] = make_float2((r == c) ? 1.f : 0.f, 0.f);
        }
        __syncthreads();

        for (int k = 10; k >= 1; k--) {
            float v = 0.f;
            if (t < 64) {
                #pragma unroll
                for (int m = 0; m < 8; m++)
                    v = fmaf(Hsm[r * 8 + m].x, Tsm[m * 8 + c].x, v);
                v = v / (float)k + ((r == c) ? 1.f : 0.f);
            }
            __syncthreads();
            if (t < 64) Tsm[t] = make_float2(v, 0.f);
            __syncthreads();
        }
        for (int sq = 0; sq < 4; sq++) {
            float v = 0.f;
            if (t < 64) {
                #pragma unroll
                for (int m = 0; m < 8; m++)
                    v = fmaf(Tsm[r * 8 + m].x, Tsm[m * 8 + c].x, v);
            }
            __syncthreads();
            if (t < 64) Tsm[t] = make_float2(v, 0.f);
            __syncthreads();
        }
        if (t < 64) g_1gr[(is_sq ? 0 : 16) + li][t] = Tsm[t].x;
        if (t < 8) {
            float sn, cn; sincosf(sio[0][t], &sn, &cn);
            g_w1[(is_sq ? 0 : 16) + li][t] = make_float2(cn, sn);
        }
    }
}

// ===========================================================================
// Main kernel pieces; in-place state, affine layout (R8).
// ===========================================================================

// K x K REAL block GEMV on one fiber with complex input-phase fold.
template<int K, int N>
__device__ __noinline__ void bs_block(const float4* __restrict__ U4,
                                      const float2* __restrict__ W,
                                      int base2, int dS)
{
    extern __shared__ float2 sm[];
    constexpr int LO = (N > 7) ? (N - 7) : 0;
    constexpr int R4 = (K <= 4) ? 1 : 2;   // float4 per padded row
    float2 inv[K];
    #pragma unroll
    for (int ci = 0; ci < K; ci++) {
        float2 s = sm[base2 + ci * dS];
        float2 w = __ldg(W + (LO + ci) * 8 + (N - LO - ci));
        inv[ci] = cmul(s, w);
    }
    #pragma unroll
    for (int a = 0; a < K; a++) {
        float2 acc = make_float2(0.f, 0.f);
        #pragma unroll
        for (int q = 0; q < R4; q++) {
            float4 u = __ldg(U4 + a * R4 + q);
            int e = 4 * q;
            rmac(acc, u.x, inv[e]);
            if (e + 1 < K) rmac(acc, u.y, inv[e + 1]);
            if (e + 2 < K) rmac(acc, u.z, inv[e + 2]);
            if (e + 3 < K) rmac(acc, u.w, inv[e + 3]);
        }
        sm[base2 + a * dS] = acc;
    }
}

// Single-mode 8x8 REAL gate + input phase; in place; 2 fibers/thread.
__device__ __noinline__ void apply1g(const float4* __restrict__ U4,
                                     const float2* __restrict__ W,
                                     int SM, int B0, int B1, int B2, int P, int t)
{
    extern __shared__ float2 sm[];
    int ba = (t & 7) * B0 + ((t >> 3) & 7) * B1 + (t >> 6) * B2;
    int bb = ba + P;
    float2 sva[8], svb[8];
    #pragma unroll
    for (int c = 0; c < 8; c++) {
        float2 w = __ldg(W + c);
        sva[c] = cmul(sm[ba + c * SM], w);
        svb[c] = cmul(sm[bb + c * SM], w);
    }
    #pragma unroll
    for (int o = 0; o < 8; o++) {
        float4 u0 = __ldg(U4 + o * 2), u1 = __ldg(U4 + o * 2 + 1);
        float2 aa = make_float2(0.f, 0.f), ab = make_float2(0.f, 0.f);
        rmac(aa, u0.x, sva[0]); rmac(aa, u0.y, sva[1]);
        rmac(aa, u0.z, sva[2]); rmac(aa, u0.w, sva[3]);
        rmac(aa, u1.x, sva[4]); rmac(aa, u1.y, sva[5]);
        rmac(aa, u1.z, sva[6]); rmac(aa, u1.w, sva[7]);
        rmac(ab, u0.x, svb[0]); rmac(ab, u0.y, svb[1]);
        rmac(ab, u0.z, svb[2]); rmac(ab, u0.w, svb[3]);
        rmac(ab, u1.x, svb[4]); rmac(ab, u1.y, svb[5]);
        rmac(ab, u1.z, svb[6]); rmac(ab, u1.w, svb[7]);
        sm[ba + o * SM] = aa; sm[bb + o * SM] = ab;
    }
}

// ===========================================================================
// Main kernel: one CTA per batch element (R8 chassis).
// ===========================================================================
__global__ __launch_bounds__(NTHR, 3) void qnn_main(
    const float* __restrict__ x, float* __restrict__ out)
{
    extern __shared__ float2 sm[];
    float* enc = (float*)(sm + ST_SIZE);   // encH[256] encA[256] encB[256] red[32]
    float* encH = enc, *encA = enc + 256, *encB = enc + 512;
    float* red = enc + 768;

    int b = blockIdx.x, t = threadIdx.x;

    // ---- per-sample encoding expm: E_g = expm(x_g (AD - A)), real 8x8 ----
    {
        int g = t >> 6, e = t & 63, r = e >> 3, c = e & 7;
        float xv = __ldg(&x[b * 4 + g]);
        float sc = xv * (1.0f / 64.0f);   // 6 squarings
        float h = 0.f;
        if (c == r - 1) h = sc * sqrtf((float)r);
        else if (c == r + 1) h = -sc * sqrtf((float)(r + 1));
        encH[g * 64 + e] = h;
        encA[g * 64 + e] = (r == c) ? 1.f : 0.f;
        __syncthreads();

        float* Ta = encA + g * 64;
        float* Tb = encB + g * 64;
        for (int k = 9; k >= 1; k--) {
            float acc = 0.f;
            #pragma unroll
            for (int m = 0; m < 8; m++)
                acc = fmaf(encH[g * 64 + r * 8 + m], Ta[m * 8 + c], acc);
            float v = acc / (float)k + ((r == c) ? 1.f : 0.f);
            Tb[e] = v;
            __syncthreads();
            float* tmp = Ta; Ta = Tb; Tb = tmp;
        }
        for (int sq = 0; sq < 6; sq++) {
            float acc = 0.f;
            #pragma unroll
            for (int m = 0; m < 8; m++) acc = fmaf(Ta[r * 8 + m], Ta[m * 8 + c], acc);
            Tb[e] = acc;
            __syncthreads();
            float* tmp = Ta; Ta = Tb; Tb = tmp;
        }
        // 15 swaps: final matrix lives in encB region
    }

    // ---- init state: outer product of E_g column 0 (vacuum input) ----
    #pragma unroll 1
    for (int q = 0; q < 16; q++) {
        int e = t * 16 + q;
        int i = e >> 9, j = (e >> 6) & 7, k = (e >> 3) & 7, l2 = e & 7;
        float v = encB[0 * 64 + i * 8] * encB[1 * 64 + j * 8]
                * encB[2 * 64 + k * 8] * encB[3 * 64 + l2 * 8];
        sm[i * S0 + j * S1 + k * S2 + l2] = make_float2(v, 0.f);
    }
    __syncthreads();

    // ---- circuit: per layer-half: 6 BS + 4 single-mode (phases chained) ----
    int f = t & 63, og = t >> 6;

    #pragma unroll 1
    for (int l = 0; l < 4; l++) {
        #pragma unroll 1
        for (int hh = 0; hh < 2; hh++) {
            #pragma unroll 1
            for (int p = 0; p < 6; p++) {
                int gate = l * 12 + hh * 6 + p;
                const float4* U4 = (const float4*)g_bsr[gate];
                const float2* W = g_wbs[gate];
                int SA = c_SA[p], SB = c_SB[p];
                int base = (f >> 3) * c_Q0[p] + (f & 7) * c_Q1v[p];
                int dS = SA - SB;
                if (og == 0) {
                    bs_block<8,7>(U4 + 46, W, base + 7 * SB, dS);
                    bs_block<4,3>(U4 + 6,  W, base + 3 * SB, dS);
                    bs_block<2,1>(U4 + 1,  W, base + 1 * SB, dS);
                    bs_block<1,0>(U4 + 0,  W, base,           dS);
                } else if (og == 1) {
                    bs_block<7,6>(U4 + 32, W, base + 6 * SB, dS);
                    bs_block<5,4>(U4 + 10, W, base + 4 * SB, dS);
                    bs_block<3,2>(U4 + 3,  W, base + 2 * SB, dS);
                    bs_block<2,13>(U4 + 105, W, base + 6 * SA + 7 * SB, dS);
                } else if (og == 2) {
                    bs_block<7,8>(U4 + 62,  W, base + 1 * SA + 7 * SB, dS);
                    bs_block<5,10>(U4 + 88, W, base + 3 * SA + 7 * SB, dS);
                    bs_block<3,12>(U4 + 102, W, base + 5 * SA + 7 * SB, dS);
                    bs_block<1,14>(U4 + 107, W, base + 7 * SA + 7 * SB, dS);
                } else {
                    bs_block<6,5>(U4 + 20, W, base + 5 * SB, dS);
                    bs_block<6,9>(U4 + 76, W, base + 2 * SA + 7 * SB, dS);
                    bs_block<4,11>(U4 + 98, W, base + 4 * SA + 7 * SB, dS);
                }
                __syncthreads();
            }
            #pragma unroll 1
            for (int w = 0; w < 4; w++) {
                int g = (hh ? 16 : 0) + l * 4 + w;
                apply1g((const float4*)g_1gr[g], g_w1[g],
                        c1g_SM[w], c1g_B0[w], c1g_B1[w], c1g_B2[w], c1g_P[w], t);
                __syncthreads();
            }
        }
    }

    // ---- expectations <n_w> (diagonal residual phases drop out of |psi|^2) ----
    float ev0 = 0.f, ev1 = 0.f, ev2 = 0.f, ev3 = 0.f;
    #pragma unroll 1
    for (int q = 0; q < 16; q++) {
        int e = t * 16 + q;
        int i = e >> 9, j = (e >> 6) & 7, k = (e >> 3) & 7, l2 = e & 7;
        float2 a = sm[i * S0 + j * S1 + k * S2 + l2];
        float p = a.x * a.x + a.y * a.y;
        ev0 = fmaf(p, (float)i, ev0);
        ev1 = fmaf(p, (float)j, ev1);
        ev2 = fmaf(p, (float)k, ev2);
        ev3 = fmaf(p, (float)l2, ev3);
    }
    #pragma unroll
    for (int off2 = 16; off2; off2 >>= 1) {
        ev0 += __shfl_down_sync(0xFFFFFFFFu, ev0, off2);
        ev1 += __shfl_down_sync(0xFFFFFFFFu, ev1, off2);
        ev2 += __shfl_down_sync(0xFFFFFFFFu, ev2, off2);
        ev3 += __shfl_down_sync(0xFFFFFFFFu, ev3, off2);
    }
    int wid = t >> 5, lid = t & 31;
    if (lid == 0) {
        red[0 * 8 + wid] = ev0; red[1 * 8 + wid] = ev1;
        red[2 * 8 + wid] = ev2; red[3 * 8 + wid] = ev3;
    }
    __syncthreads();
    if (t < 4) {
        float s = 0.f;
        #pragma unroll
        for (int wv = 0; wv < 8; wv++) s += red[t * 8 + wv];
        out[b * 4 + t] = s;
    }
}

extern "C" void kernel_launch(void* const* d_in, const int* in_sizes, int n_in,
                              void* d_out, int out_size) {
    const float* x    = (const float*)d_in[0];
    const float* th1  = (const float*)d_in[1];
    const float* ph1  = (const float*)d_in[2];
    const float* th2  = (const float*)d_in[3];
    const float* ph2  = (const float*)d_in[4];
    const float* dr   = (const float*)d_in[5];
    const float* dphi = (const float*)d_in[6];
    const float* sr   = (const float*)d_in[7];
    const float* sphi = (const float*)d_in[8];
    const float* kerr = (const float*)d_in[9];
    float* out = (float*)d_out;
    int Bn = in_sizes[0] / 4;

    int smem_bytes = ST_SIZE * (int)sizeof(float2) + (768 + 32) * (int)sizeof(float);
    cudaFuncSetAttribute(qnn_main, cudaFuncAttributeMaxDynamicSharedMemorySize, smem_bytes);

    precompute_kernel<<<80, NTHR>>>(th1, ph1, th2, ph2, dr, dphi, sr, sphi, kerr);
    qnn_main<<<Bn, NTHR, smem_bytes>>>(x, out);
}